// round 7
// baseline (speedup 1.0000x reference)
#include <cuda_runtime.h>
#include <cuda_fp16.h>
#include <cstdint>
#include <math.h>

// ---------------- problem constants ----------------
#define BATCH    16384
#define F_IN     768
#define F_OUT    512
#define BM       64            // batch rows per CTA
#define BN       256           // output cols per CTA (N split across 2 CTAs)
#define BK       64            // K chunk
#define NCHUNK   (F_IN / BK)   // 12 chunks per pass
#define NPASS    2
#define TOTCHUNK (NCHUNK * NPASS)  // 24
#define NTHREADS 256
#define MTILES   (BATCH / BM)  // 256

// ---------------- smem layout (bytes), per CTA = 86016 (2 fit per SM) ----------------
#define SM_BIAS  0                     // 256 f32 = 1024
#define SM_W2    1024                  // 512 f32 = 2048
#define SM_RED   3072                  // 64 f32 = 256
#define SM_A0    4096                  // 2 stages x 8192 (64 rows x 128B)
#define SM_B     20480                 // 2 stages x 32768 (256 rows x 128B)
#define SM_TOTAL (SM_B + 2 * 32768)    // 86016

// ---------------- helpers ----------------
__device__ __forceinline__ uint32_t smem_u32(const void* p) {
    uint32_t a;
    asm("{ .reg .u64 t; cvta.to.shared.u64 t, %1; cvt.u32.u64 %0, t; }" : "=r"(a) : "l"(p));
    return a;
}

#define LDSM_X4(r0, r1, r2, r3, addr) \
    asm volatile("ldmatrix.sync.aligned.m8n8.x4.shared.b16 {%0,%1,%2,%3}, [%4];" \
                 : "=r"(r0), "=r"(r1), "=r"(r2), "=r"(r3) : "r"(addr))

#define MMA16816(d, a, b) \
    asm volatile("mma.sync.aligned.m16n8k16.row.col.f32.f16.f16.f32 " \
                 "{%0,%1,%2,%3}, {%4,%5,%6,%7}, {%8,%9}, {%0,%1,%2,%3};" \
                 : "+f"((d)[0]), "+f"((d)[1]), "+f"((d)[2]), "+f"((d)[3]) \
                 : "r"((a)[0]), "r"((a)[1]), "r"((a)[2]), "r"((a)[3]), \
                   "r"((b)[0]), "r"((b)[1]))

#define CP_ASYNC16(dst, src) \
    asm volatile("cp.async.cg.shared.global [%0], [%1], 16;" :: "r"(dst), "l"(src) : "memory")
#define CP_COMMIT() asm volatile("cp.async.commit_group;" ::: "memory")
#define CP_WAIT0()  asm volatile("cp.async.wait_group 0;" ::: "memory")

// cvt 8 f32 -> 8 f16, one swizzled 16B STS
__device__ __forceinline__ void sts_a16(uint32_t addr, float4 v0, float4 v1) {
    uint32_t u0, u1, u2, u3;
    asm("cvt.rn.f16x2.f32 %0, %1, %2;" : "=r"(u0) : "f"(v0.y), "f"(v0.x));
    asm("cvt.rn.f16x2.f32 %0, %1, %2;" : "=r"(u1) : "f"(v0.w), "f"(v0.z));
    asm("cvt.rn.f16x2.f32 %0, %1, %2;" : "=r"(u2) : "f"(v1.y), "f"(v1.x));
    asm("cvt.rn.f16x2.f32 %0, %1, %2;" : "=r"(u3) : "f"(v1.w), "f"(v1.z));
    asm volatile("st.shared.v4.u32 [%0], {%1,%2,%3,%4};"
                 :: "r"(addr), "r"(u0), "r"(u1), "r"(u2), "r"(u3) : "memory");
}

// ---------------- device globals ----------------
__device__ __align__(16) __half g_W1h[F_OUT * F_IN];
__device__ float g_part0[BATCH];   // partial dot from N-half 0 (written once per launch)
__device__ float g_part1[BATCH];   // partial dot from N-half 1

__global__ void convert_w1_kernel(const float* __restrict__ W1) {
    int i = blockIdx.x * blockDim.x + threadIdx.x;
    const int n = F_OUT * F_IN / 2;
    if (i < n) {
        float2 v = reinterpret_cast<const float2*>(W1)[i];
        reinterpret_cast<__half2*>(g_W1h)[i] = __floats2half2_rn(v.x, v.y);
    }
}

__global__ void finalize_kernel(const float* __restrict__ b2, float* __restrict__ out) {
    int i = blockIdx.x * blockDim.x + threadIdx.x;
    if (i < BATCH) {
        float z = g_part0[i] + g_part1[i] + b2[0];
        out[i] = 1.0f / (1.0f + expf(-z));
    }
}

// ---------------- fused perspective-network kernel ----------------
// grid (256, 2): x = M tile, y = N half. 8 warps: warpM = wid>>2, warpN = wid&3.
// 2 CTAs co-resident per SM (86KB smem, <=128 regs).
__global__ void __launch_bounds__(NTHREADS, 2)
persp_kernel(const float* __restrict__ stm, const float* __restrict__ nstm,
             const float* __restrict__ b1, const float* __restrict__ W2) {
    extern __shared__ __align__(1024) char smem[];
    const uint32_t sb = smem_u32(smem);
    const int tid  = threadIdx.x;
    const int lane = tid & 31;
    const int wid  = tid >> 5;
    const int warpM = wid >> 2;    // 0..1 (32 rows)
    const int warpN = wid & 3;     // 0..3 (64 cols)
    const int m0  = blockIdx.x * BM;
    const int nb0 = blockIdx.y * BN;

    float* bias_s = reinterpret_cast<float*>(smem + SM_BIAS);
    float* w2_s   = reinterpret_cast<float*>(smem + SM_W2);
    float* red_s  = reinterpret_cast<float*>(smem + SM_RED);

    if (tid < BN) bias_s[tid] = b1[nb0 + tid];
    for (int i = tid; i < 2 * BN; i += NTHREADS)
        w2_s[i] = W2[(i >> 8) * F_OUT + nb0 + (i & (BN - 1))];
    if (tid < BM) red_s[tid] = 0.0f;

    // ---- ldmatrix per-lane geometry ----
    const int aRow   = warpM * 32 + ((lane >> 3) & 1) * 8 + (lane & 7);
    const uint32_t aXor = ((uint32_t)(lane >> 4) * 16) ^ ((uint32_t)(aRow & 7) << 4);
    const uint32_t aOff = aRow * 128;
    const int bRow   = warpN * 64 + ((lane >> 4) & 1) * 8 + (lane & 7);
    const uint32_t bXor = (((uint32_t)(lane >> 3) & 1) * 16) ^ ((uint32_t)(bRow & 7) << 4);
    const uint32_t bOff = bRow * 128;

    // ---- global->smem fill geometry ----
    // A: 64 rows x 64 f32; thread -> row tid>>2, 16 cols at (tid&3)*16
    const int aRowG = tid >> 2;
    const int aSeg  = tid & 3;
    const uint32_t aSts0 = aRowG * 128 + (((uint32_t)aSeg * 32)      ^ ((uint32_t)(aRowG & 7) << 4));
    const uint32_t aSts1 = aRowG * 128 + (((uint32_t)aSeg * 32 + 16) ^ ((uint32_t)(aRowG & 7) << 4));
    // B: 256 rows x 64 f16; thread -> rows (tid>>3)+32j, 16B seg tid&7
    const int bRow0 = tid >> 3;             // 0..31
    const int bSeg  = tid & 7;
    const uint32_t bDstBase = bRow0 * 128 + (((uint32_t)bSeg * 16) ^ ((uint32_t)(bRow0 & 7) << 4));
    const __half* bSrcBase = g_W1h + (size_t)(nb0 + bRow0) * F_IN + bSeg * 8;

    float acc[2][8][4] = {};
    float rowsum[4] = {0.f, 0.f, 0.f, 0.f};
    float4 sA[4];   // staged A regs (16 floats, next chunk)

    // ---- prologue: fill stage0 (chunk 0), stage A regs (chunk 1) ----
    {
#pragma unroll
        for (int j = 0; j < 8; ++j)
            CP_ASYNC16(sb + SM_B + bDstBase + j * 4096, bSrcBase + (size_t)j * 32 * F_IN);
        CP_COMMIT();
        const float4* s0 = reinterpret_cast<const float4*>(
            stm + (size_t)(m0 + aRowG) * F_IN + aSeg * 16);
        float4 v0 = s0[0], v1 = s0[1], v2 = s0[2], v3 = s0[3];
        sts_a16(sb + SM_A0 + aSts0, v0, v1);
        sts_a16(sb + SM_A0 + aSts1, v2, v3);
        const float4* s1 = reinterpret_cast<const float4*>(
            stm + (size_t)(m0 + aRowG) * F_IN + BK + aSeg * 16);
        sA[0] = s1[0]; sA[1] = s1[1]; sA[2] = s1[2]; sA[3] = s1[3];
        CP_WAIT0();
        __syncthreads();
    }

    for (int g = 0; g < TOTCHUNK; ++g) {
        const int p = g & 1;
        const uint32_t bufA  = sb + SM_A0 + p * 8192;
        const uint32_t bufB  = sb + SM_B  + p * 32768;
        const uint32_t bufAn = sb + SM_A0 + (p ^ 1) * 8192;
        const uint32_t bufBn = sb + SM_B  + (p ^ 1) * 32768;

        // prefetch chunk g+1: staged A -> smem, B via cp.async
        if (g + 1 < TOTCHUNK) {
            sts_a16(bufAn + aSts0, sA[0], sA[1]);
            sts_a16(bufAn + aSts1, sA[2], sA[3]);
            const int c1 = (g + 1) % NCHUNK;
            const __half* src = bSrcBase + c1 * BK;
#pragma unroll
            for (int j = 0; j < 8; ++j)
                CP_ASYNC16(bufBn + bDstBase + j * 4096, src + (size_t)j * 32 * F_IN);
            CP_COMMIT();
        }
        // LDG chunk g+2 into staging registers (lands during compute)
        if (g + 2 < TOTCHUNK) {
            const int g2 = g + 2;
            const float* X = (g2 >= NCHUNK) ? nstm : stm;
            const float4* s = reinterpret_cast<const float4*>(
                X + (size_t)(m0 + aRowG) * F_IN + (g2 % NCHUNK) * BK + aSeg * 16);
            sA[0] = s[0]; sA[1] = s[1]; sA[2] = s[2]; sA[3] = s[3];
        }

        // ---- compute chunk g ----
#pragma unroll
        for (int ks = 0; ks < 4; ++ks) {
            const uint32_t kx = (uint32_t)(ks << 5);
            uint32_t a0[4], a1[4];
            LDSM_X4(a0[0], a0[1], a0[2], a0[3], bufA + aOff +        (aXor ^ kx));
            LDSM_X4(a1[0], a1[1], a1[2], a1[3], bufA + aOff + 2048 + (aXor ^ kx));
            uint32_t b[8][2];
#pragma unroll
            for (int nt2 = 0; nt2 < 4; ++nt2) {
                uint32_t r0, r1, r2, r3;
                LDSM_X4(r0, r1, r2, r3, bufB + bOff + nt2 * 2048 + (bXor ^ kx));
                b[nt2 * 2][0] = r0;     b[nt2 * 2][1] = r1;
                b[nt2 * 2 + 1][0] = r2; b[nt2 * 2 + 1][1] = r3;
            }
#pragma unroll
            for (int nt = 0; nt < 8; ++nt) {
                MMA16816(acc[0][nt], a0, b[nt]);
                MMA16816(acc[1][nt], a1, b[nt]);
            }
        }

        // ---- end-of-pass: bias + clip + W2 partial dot, reset acc ----
        if (g == NCHUNK - 1 || g == TOTCHUNK - 1) {
            const int w2o = (g >= NCHUNK) ? BN : 0;
#pragma unroll
            for (int mt = 0; mt < 2; ++mt) {
#pragma unroll
                for (int nt = 0; nt < 8; ++nt) {
                    const int nb = warpN * 64 + nt * 8 + (lane & 3) * 2;
                    const float ba = bias_s[nb],      bb = bias_s[nb + 1];
                    const float wa = w2_s[w2o + nb],  wb = w2_s[w2o + nb + 1];
                    float h;
                    h = fminf(fmaxf(acc[mt][nt][0] + ba, 0.f), 1.f); rowsum[mt*2+0] = fmaf(h, wa, rowsum[mt*2+0]);
                    h = fminf(fmaxf(acc[mt][nt][1] + bb, 0.f), 1.f); rowsum[mt*2+0] = fmaf(h, wb, rowsum[mt*2+0]);
                    h = fminf(fmaxf(acc[mt][nt][2] + ba, 0.f), 1.f); rowsum[mt*2+1] = fmaf(h, wa, rowsum[mt*2+1]);
                    h = fminf(fmaxf(acc[mt][nt][3] + bb, 0.f), 1.f); rowsum[mt*2+1] = fmaf(h, wb, rowsum[mt*2+1]);
                    acc[mt][nt][0] = 0.f; acc[mt][nt][1] = 0.f;
                    acc[mt][nt][2] = 0.f; acc[mt][nt][3] = 0.f;
                }
            }
        }

        CP_WAIT0();
        __syncthreads();
    }

    // ---- cross-lane + cross-warp reduce, write partial ----
#pragma unroll
    for (int r = 0; r < 4; ++r) {
        float v = rowsum[r];
        v += __shfl_xor_sync(0xFFFFFFFFu, v, 1);
        v += __shfl_xor_sync(0xFFFFFFFFu, v, 2);
        if ((lane & 3) == 0) {
            const int row = warpM * 32 + (r >> 1) * 16 + (r & 1) * 8 + (lane >> 2);
            atomicAdd(&red_s[row], v);
        }
    }
    __syncthreads();
    if (tid < BM) {
        float* gp = blockIdx.y ? g_part1 : g_part0;
        gp[m0 + tid] = red_s[tid];
    }
}

// ---------------- launch ----------------
extern "C" void kernel_launch(void* const* d_in, const int* in_sizes, int n_in,
                              void* d_out, int out_size) {
    const float* stm  = (const float*)d_in[0];
    const float* nstm = (const float*)d_in[1];
    const float* W1   = (const float*)d_in[2];
    const float* b1   = (const float*)d_in[3];
    const float* W2   = (const float*)d_in[4];
    const float* b2   = (const float*)d_in[5];
    float* out = (float*)d_out;

    cudaFuncSetAttribute(persp_kernel, cudaFuncAttributeMaxDynamicSharedMemorySize, SM_TOTAL);

    const int nconv = F_OUT * F_IN / 2;
    convert_w1_kernel<<<(nconv + 255) / 256, 256>>>(W1);
    persp_kernel<<<dim3(MTILES, 2), NTHREADS, SM_TOTAL>>>(stm, nstm, b1, W2);
    finalize_kernel<<<(BATCH + 255) / 256, 256>>>(b2, out);
}

// round 8
// speedup vs baseline: 1.0698x; 1.0698x over previous
#include <cuda_runtime.h>
#include <cuda_fp16.h>
#include <cstdint>
#include <math.h>

// ---------------- problem constants ----------------
#define BATCH    16384
#define F_IN     768
#define F_OUT    512
#define BM       64            // batch rows per CTA
#define BK       64            // K chunk
#define NCHUNK   (F_IN / BK)   // 12 chunks per pass
#define NPASS    2
#define TOTCHUNK (NCHUNK * NPASS)  // 24
#define NTHREADS 256
#define CTAS     (BATCH / BM)  // 256

// ---------------- smem layout (bytes) ----------------
#define SM_BIAS  0                     // 512 f32 = 2048
#define SM_W2    2048                  // 1024 f32 = 4096
#define SM_RED   6144                  // 64 f32 = 256
#define SM_A0    8192                  // 2 stages x 8192 (64 rows x 128B)
#define SM_B     24576                 // 2 stages x 65536 (512 rows x 128B)
#define SM_TOTAL (SM_B + 2 * 65536)    // 155648

// ---------------- helpers ----------------
__device__ __forceinline__ uint32_t smem_u32(const void* p) {
    uint32_t a;
    asm("{ .reg .u64 t; cvta.to.shared.u64 t, %1; cvt.u32.u64 %0, t; }" : "=r"(a) : "l"(p));
    return a;
}

#define LDSM_X4(r0, r1, r2, r3, addr) \
    asm volatile("ldmatrix.sync.aligned.m8n8.x4.shared.b16 {%0,%1,%2,%3}, [%4];" \
                 : "=r"(r0), "=r"(r1), "=r"(r2), "=r"(r3) : "r"(addr))

#define MMA16816(d, a, b) \
    asm volatile("mma.sync.aligned.m16n8k16.row.col.f32.f16.f16.f32 " \
                 "{%0,%1,%2,%3}, {%4,%5,%6,%7}, {%8,%9}, {%0,%1,%2,%3};" \
                 : "+f"((d)[0]), "+f"((d)[1]), "+f"((d)[2]), "+f"((d)[3]) \
                 : "r"((a)[0]), "r"((a)[1]), "r"((a)[2]), "r"((a)[3]), \
                   "r"((b)[0]), "r"((b)[1]))

#define CP_ASYNC16(dst, src) \
    asm volatile("cp.async.cg.shared.global [%0], [%1], 16;" :: "r"(dst), "l"(src) : "memory")
#define CP_COMMIT() asm volatile("cp.async.commit_group;" ::: "memory")
#define CP_WAIT0()  asm volatile("cp.async.wait_group 0;" ::: "memory")

// cvt 8 f32 -> 8 f16, one swizzled 16B STS
__device__ __forceinline__ void sts_a16(uint32_t addr, float4 v0, float4 v1) {
    uint32_t u0, u1, u2, u3;
    asm("cvt.rn.f16x2.f32 %0, %1, %2;" : "=r"(u0) : "f"(v0.y), "f"(v0.x));
    asm("cvt.rn.f16x2.f32 %0, %1, %2;" : "=r"(u1) : "f"(v0.w), "f"(v0.z));
    asm("cvt.rn.f16x2.f32 %0, %1, %2;" : "=r"(u2) : "f"(v1.y), "f"(v1.x));
    asm("cvt.rn.f16x2.f32 %0, %1, %2;" : "=r"(u3) : "f"(v1.w), "f"(v1.z));
    asm volatile("st.shared.v4.u32 [%0], {%1,%2,%3,%4};"
                 :: "r"(addr), "r"(u0), "r"(u1), "r"(u2), "r"(u3) : "memory");
}

// ---------------- W1 fp32 -> fp16 pre-conversion ----------------
__device__ __align__(16) __half g_W1h[F_OUT * F_IN];

__global__ void convert_w1_kernel(const float* __restrict__ W1) {
    int i = blockIdx.x * blockDim.x + threadIdx.x;
    const int n = F_OUT * F_IN / 4;
    if (i < n) {
        float4 v = reinterpret_cast<const float4*>(W1)[i];
        __half2 h0 = __floats2half2_rn(v.x, v.y);
        __half2 h1 = __floats2half2_rn(v.z, v.w);
        reinterpret_cast<__half2*>(g_W1h)[i * 2]     = h0;
        reinterpret_cast<__half2*>(g_W1h)[i * 2 + 1] = h1;
    }
}

// ---------------- fused perspective-network kernel ----------------
// 8 warps, each owns a 64x64 output tile: warpN = wid (cols wid*64..wid*64+63),
// all 64 batch rows. Fragments register-double-buffered across ks iterations.
__global__ void __launch_bounds__(NTHREADS, 1)
persp_kernel(const float* __restrict__ stm, const float* __restrict__ nstm,
             const float* __restrict__ b1, const float* __restrict__ W2,
             const float* __restrict__ b2, float* __restrict__ out) {
    extern __shared__ __align__(1024) char smem[];
    const uint32_t sb = smem_u32(smem);
    const int tid   = threadIdx.x;
    const int lane  = tid & 31;
    const int warpN = tid >> 5;    // 0..7
    const int m0 = blockIdx.x * BM;

    float* bias_s = reinterpret_cast<float*>(smem + SM_BIAS);
    float* w2_s   = reinterpret_cast<float*>(smem + SM_W2);
    float* red_s  = reinterpret_cast<float*>(smem + SM_RED);

    for (int i = tid; i < F_OUT; i += NTHREADS)     bias_s[i] = b1[i];
    for (int i = tid; i < 2 * F_OUT; i += NTHREADS) w2_s[i]   = W2[i];
    if (tid < BM) red_s[tid] = 0.0f;

    // ---- ldmatrix per-lane geometry ----
    // A 16x16 tile (mt steps of 16 rows): in-tile row + k-half xor
    const uint32_t aInOff = (uint32_t)(((lane >> 3) & 1) * 8 + (lane & 7)) * 128;
    const uint32_t aXor   = ((uint32_t)(lane >> 4) * 16) ^ ((uint32_t)(lane & 7) << 4);
    // B (W1h rows = n): base row for this warp; nt2 steps of 16 rows
    const uint32_t bInOff = (uint32_t)(warpN * 64 + ((lane >> 4) & 1) * 8 + (lane & 7)) * 128;
    const uint32_t bXor   = (((uint32_t)(lane >> 3) & 1) * 16) ^ ((uint32_t)(lane & 7) << 4);

    // ---- global->smem fill geometry ----
    // A: 64 rows x 64 f32; thread -> row tid>>2, 16 floats at (tid&3)*16
    const int aRowG = tid >> 2;
    const int aSeg  = tid & 3;
    const uint32_t aSts0 = aRowG * 128 + (((uint32_t)aSeg * 32)      ^ ((uint32_t)(aRowG & 7) << 4));
    const uint32_t aSts1 = aRowG * 128 + (((uint32_t)aSeg * 32 + 16) ^ ((uint32_t)(aRowG & 7) << 4));
    // B: 512 rows x 64 f16; thread -> rows (tid>>3)+32j (j<16), 16B seg tid&7
    const int bRow0 = tid >> 3;             // 0..31
    const int bSeg  = tid & 7;
    const uint32_t bDstBase = bRow0 * 128 + (((uint32_t)bSeg * 16) ^ ((uint32_t)(bRow0 & 7) << 4));
    const __half* bSrcBase = g_W1h + (size_t)bRow0 * F_IN + bSeg * 8;

    float acc[4][8][4] = {};
    float rowsum[8] = {0.f, 0.f, 0.f, 0.f, 0.f, 0.f, 0.f, 0.f};
    float4 sA[4];                 // staged A regs (16 floats) for chunk g+2
    uint32_t aa[2][4][4];         // A fragments, double buffered across ks
    uint32_t bb[2][8][2];         // B fragments

#define LOAD_FRAGS(kq, pb, bufA_, bufB_) do {                                     \
    const uint32_t kx_ = (uint32_t)((kq) << 5);                                   \
    _Pragma("unroll")                                                             \
    for (int mt_ = 0; mt_ < 4; ++mt_)                                             \
        LDSM_X4(aa[pb][mt_][0], aa[pb][mt_][1], aa[pb][mt_][2], aa[pb][mt_][3],   \
                (bufA_) + mt_ * 2048 + aInOff + (aXor ^ kx_));                    \
    _Pragma("unroll")                                                             \
    for (int nt2_ = 0; nt2_ < 4; ++nt2_) {                                        \
        uint32_t r0_, r1_, r2_, r3_;                                              \
        LDSM_X4(r0_, r1_, r2_, r3_, (bufB_) + bInOff + nt2_ * 2048 + (bXor ^ kx_)); \
        bb[pb][nt2_ * 2][0] = r0_;     bb[pb][nt2_ * 2][1] = r1_;                 \
        bb[pb][nt2_ * 2 + 1][0] = r2_; bb[pb][nt2_ * 2 + 1][1] = r3_;             \
    }                                                                             \
} while (0)

    // ---- prologue: fill stage0 (chunk 0), stage A regs (chunk 1) ----
    {
#pragma unroll
        for (int j = 0; j < 16; ++j)
            CP_ASYNC16(sb + SM_B + bDstBase + j * 4096, bSrcBase + (size_t)j * 32 * F_IN);
        CP_COMMIT();
        const float4* s0 = reinterpret_cast<const float4*>(
            stm + (size_t)(m0 + aRowG) * F_IN + aSeg * 16);
        sts_a16(sb + SM_A0 + aSts0, s0[0], s0[1]);
        sts_a16(sb + SM_A0 + aSts1, s0[2], s0[3]);
        const float4* s1 = reinterpret_cast<const float4*>(
            stm + (size_t)(m0 + aRowG) * F_IN + BK + aSeg * 16);
        sA[0] = s1[0]; sA[1] = s1[1]; sA[2] = s1[2]; sA[3] = s1[3];
        CP_WAIT0();
        __syncthreads();
    }

    for (int g = 0; g < TOTCHUNK; ++g) {
        const int p = g & 1;
        const uint32_t bufA  = sb + SM_A0 + p * 8192;
        const uint32_t bufB  = sb + SM_B  + p * 65536;
        const uint32_t bufAn = sb + SM_A0 + (p ^ 1) * 8192;
        const uint32_t bufBn = sb + SM_B  + (p ^ 1) * 65536;

        // first fragment set for this chunk (overlaps with prefetch issue below)
        LOAD_FRAGS(0, 0, bufA, bufB);

        // prefetch chunk g+1: staged A -> smem, B via cp.async
        if (g + 1 < TOTCHUNK) {
            sts_a16(bufAn + aSts0, sA[0], sA[1]);
            sts_a16(bufAn + aSts1, sA[2], sA[3]);
            const int c1 = (g + 1) % NCHUNK;
            const __half* src = bSrcBase + c1 * BK;
#pragma unroll
            for (int j = 0; j < 16; ++j)
                CP_ASYNC16(bufBn + bDstBase + j * 4096, src + (size_t)j * 32 * F_IN);
            CP_COMMIT();
        }
        // LDG chunk g+2 into staging registers (lands during compute)
        if (g + 2 < TOTCHUNK) {
            const int g2 = g + 2;
            const float* X = (g2 >= NCHUNK) ? nstm : stm;
            const float4* s = reinterpret_cast<const float4*>(
                X + (size_t)(m0 + aRowG) * F_IN + (g2 % NCHUNK) * BK + aSeg * 16);
            sA[0] = s[0]; sA[1] = s[1]; sA[2] = s[2]; sA[3] = s[3];
        }

        // ---- compute chunk g, fragments double-buffered across ks ----
#pragma unroll
        for (int ks = 0; ks < 4; ++ks) {
            const int cur = ks & 1;
            if (ks < 3) LOAD_FRAGS(ks + 1, cur ^ 1, bufA, bufB);
#pragma unroll
            for (int mt = 0; mt < 4; ++mt)
#pragma unroll
                for (int nt = 0; nt < 8; ++nt)
                    MMA16816(acc[mt][nt], aa[cur][mt], bb[cur][nt]);
        }

        // ---- end-of-pass: bias + clip + W2 partial dot, reset acc ----
        if (g == NCHUNK - 1 || g == TOTCHUNK - 1) {
            const int w2o = (g >= NCHUNK) ? F_OUT : 0;
#pragma unroll
            for (int mt = 0; mt < 4; ++mt) {
#pragma unroll
                for (int nt = 0; nt < 8; ++nt) {
                    const int nb = warpN * 64 + nt * 8 + (lane & 3) * 2;
                    const float ba = bias_s[nb],      bbi = bias_s[nb + 1];
                    const float wa = w2_s[w2o + nb],  wb  = w2_s[w2o + nb + 1];
                    float h;
                    h = fminf(fmaxf(acc[mt][nt][0] + ba,  0.f), 1.f); rowsum[mt*2+0] = fmaf(h, wa, rowsum[mt*2+0]);
                    h = fminf(fmaxf(acc[mt][nt][1] + bbi, 0.f), 1.f); rowsum[mt*2+0] = fmaf(h, wb, rowsum[mt*2+0]);
                    h = fminf(fmaxf(acc[mt][nt][2] + ba,  0.f), 1.f); rowsum[mt*2+1] = fmaf(h, wa, rowsum[mt*2+1]);
                    h = fminf(fmaxf(acc[mt][nt][3] + bbi, 0.f), 1.f); rowsum[mt*2+1] = fmaf(h, wb, rowsum[mt*2+1]);
                    acc[mt][nt][0] = 0.f; acc[mt][nt][1] = 0.f;
                    acc[mt][nt][2] = 0.f; acc[mt][nt][3] = 0.f;
                }
            }
        }

        CP_WAIT0();
        __syncthreads();
    }

    // ---- cross-lane + cross-warp reduce, sigmoid, store ----
#pragma unroll
    for (int r = 0; r < 8; ++r) {
        float v = rowsum[r];
        v += __shfl_xor_sync(0xFFFFFFFFu, v, 1);
        v += __shfl_xor_sync(0xFFFFFFFFu, v, 2);
        if ((lane & 3) == 0) {
            const int row = (r >> 1) * 16 + (r & 1) * 8 + (lane >> 2);
            atomicAdd(&red_s[row], v);
        }
    }
    __syncthreads();
    if (tid < BM) {
        const float z = red_s[tid] + b2[0];
        out[m0 + tid] = 1.0f / (1.0f + expf(-z));
    }
}

// ---------------- launch ----------------
extern "C" void kernel_launch(void* const* d_in, const int* in_sizes, int n_in,
                              void* d_out, int out_size) {
    const float* stm  = (const float*)d_in[0];
    const float* nstm = (const float*)d_in[1];
    const float* W1   = (const float*)d_in[2];
    const float* b1   = (const float*)d_in[3];
    const float* W2   = (const float*)d_in[4];
    const float* b2   = (const float*)d_in[5];
    float* out = (float*)d_out;

    cudaFuncSetAttribute(persp_kernel, cudaFuncAttributeMaxDynamicSharedMemorySize, SM_TOTAL);

    const int nconv = F_OUT * F_IN / 4;
    convert_w1_kernel<<<(nconv + 255) / 256, 256>>>(W1);
    persp_kernel<<<CTAS, NTHREADS, SM_TOTAL>>>(stm, nstm, b1, W2, b2, out);
}